// round 1
// baseline (speedup 1.0000x reference)
#include <cuda_runtime.h>
#include <cstdint>

#define BATCH 16
#define CDIM 256
#define NPIX 10000
#define KDET 100
#define KREC 25
#define GTOK 16
#define DET_BLOCKS ((BATCH*KDET)/GTOK)   /* 100 */
#define REC_BLOCKS ((BATCH*KREC)/GTOK)   /* 25  */

// ---------------- scratch (static device globals; no allocation) ----------------
__device__ float g_pos[CDIM * NPIX];      // resized positional embedding [C, N]
__device__ float g_pp[6 * NPIX];          // pos projections onto Wc(2)+Wb(4) rows
__device__ float g_conf[BATCH * NPIX];    // margin l1-l0 (monotone with softmax conf)
__device__ int   g_idx[BATCH * KDET];     // top-100 indices per batch (sorted)

// ---------------- kernel A1: bilinear resize 50x50 -> 100x100 ----------------
__global__ void pos_resize_kernel(const float* __restrict__ pe) {
    int i = blockIdx.x * blockDim.x + threadIdx.x;
    if (i >= CDIM * NPIX) return;
    int c = i / NPIX, pix = i % NPIX;
    int y = pix / 100, x = pix % 100;
    float sy = (y + 0.5f) * 0.5f - 0.5f; sy = fminf(fmaxf(sy, 0.f), 49.f);
    int y0 = (int)floorf(sy); int y1 = min(y0 + 1, 49); float ty = sy - (float)y0;
    float sx = (x + 0.5f) * 0.5f - 0.5f; sx = fminf(fmaxf(sx, 0.f), 49.f);
    int x0 = (int)floorf(sx); int x1 = min(x0 + 1, 49); float tx = sx - (float)x0;
    const float* p = pe + c * 2500;
    float v00 = p[y0 * 50 + x0], v01 = p[y0 * 50 + x1];
    float v10 = p[y1 * 50 + x0], v11 = p[y1 * 50 + x1];
    float r0 = v00 * (1.f - ty) + v10 * ty;
    float r1 = v01 * (1.f - ty) + v11 * ty;
    g_pos[i] = r0 * (1.f - tx) + r1 * tx;
}

// ---------------- kernel A2: project pos onto the 6 head weight rows ----------------
__global__ void pos_proj_kernel(const float* __restrict__ Wc, const float* __restrict__ Wb) {
    __shared__ float ws[6 * 256];
    int tid = threadIdx.x;
    for (int i = tid; i < 2 * 256; i += blockDim.x) ws[i] = Wc[i];
    for (int i = tid; i < 4 * 256; i += blockDim.x) ws[512 + i] = Wb[i];
    __syncthreads();
    int n = blockIdx.x * blockDim.x + tid;
    if (n >= NPIX) return;
    float a0 = 0, a1 = 0, a2 = 0, a3 = 0, a4 = 0, a5 = 0;
    #pragma unroll 4
    for (int c = 0; c < 256; c++) {
        float p = g_pos[c * NPIX + n];
        a0 += p * ws[c];        a1 += p * ws[256 + c];
        a2 += p * ws[512 + c];  a3 += p * ws[768 + c];
        a4 += p * ws[1024 + c]; a5 += p * ws[1280 + c];
    }
    g_pp[0 * NPIX + n] = a0; g_pp[1 * NPIX + n] = a1; g_pp[2 * NPIX + n] = a2;
    g_pp[3 * NPIX + n] = a3; g_pp[4 * NPIX + n] = a4; g_pp[5 * NPIX + n] = a5;
}

// ---------------- kernel B: stream x once; emit cls, bbox, margin ----------------
__global__ void main_pass_kernel(const float* __restrict__ x,
                                 const float* __restrict__ Wc, const float* __restrict__ bc,
                                 const float* __restrict__ Wb, const float* __restrict__ bb,
                                 float* __restrict__ out_cls, float* __restrict__ out_bb) {
    __shared__ float ws[6 * 256];
    int tid = threadIdx.x;
    for (int i = tid; i < 2 * 256; i += blockDim.x) ws[i] = Wc[i];
    for (int i = tid; i < 4 * 256; i += blockDim.x) ws[512 + i] = Wb[i];
    __syncthreads();
    int id = blockIdx.x * blockDim.x + tid;
    if (id >= BATCH * NPIX) return;
    int b = id / NPIX, n = id % NPIX;
    const float* xp = x + (size_t)b * CDIM * NPIX + n;
    float a0 = 0, a1 = 0, a2 = 0, a3 = 0, a4 = 0, a5 = 0;
    #pragma unroll 8
    for (int c = 0; c < 256; c++) {
        float v = __ldg(xp + (size_t)c * NPIX);
        a0 += v * ws[c];        a1 += v * ws[256 + c];
        a2 += v * ws[512 + c];  a3 += v * ws[768 + c];
        a4 += v * ws[1024 + c]; a5 += v * ws[1280 + c];
    }
    float l0 = a0 + g_pp[0 * NPIX + n] + bc[0];
    float l1 = a1 + g_pp[1 * NPIX + n] + bc[1];
    size_t co = (size_t)b * NPIX * 2 + (size_t)n * 2;
    out_cls[co + 0] = l0;
    out_cls[co + 1] = l1;
    size_t bo = (size_t)b * NPIX * 4 + (size_t)n * 4;
    out_bb[bo + 0] = a2 + g_pp[2 * NPIX + n] + bb[0];
    out_bb[bo + 1] = a3 + g_pp[3 * NPIX + n] + bb[1];
    out_bb[bo + 2] = a4 + g_pp[4 * NPIX + n] + bb[2];
    out_bb[bo + 3] = a5 + g_pp[5 * NPIX + n] + bb[3];
    g_conf[b * NPIX + n] = l1 - l0;   // monotone with softmax(...)[...,1]
}

// ---------------- kernel C: exact per-batch top-100 (value desc, index asc) ----------------
__global__ void __launch_bounds__(1024) topk_kernel() {
    __shared__ unsigned int keys[NPIX];
    __shared__ unsigned int hist[256];
    __shared__ unsigned long long cand[256];
    __shared__ unsigned int s_prefix;
    __shared__ int s_kk, s_cnt;
    int b = blockIdx.x, tid = threadIdx.x;

    for (int i = tid; i < NPIX; i += 1024) {
        unsigned u = __float_as_uint(g_conf[b * NPIX + i]);
        keys[i] = (u & 0x80000000u) ? ~u : (u | 0x80000000u);
    }
    if (tid == 0) { s_prefix = 0u; s_kk = KDET; }
    __syncthreads();

    // 4-pass MSB radix select for the 100th-largest key
    for (int pass = 0; pass < 4; pass++) {
        int shift = 24 - 8 * pass;
        unsigned himask = (pass == 0) ? 0u : (0xFFFFFFFFu << (shift + 8));
        for (int i = tid; i < 256; i += 1024) hist[i] = 0;
        __syncthreads();
        unsigned prefix = s_prefix;
        for (int i = tid; i < NPIX; i += 1024) {
            unsigned u = keys[i];
            if (((u ^ prefix) & himask) == 0) atomicAdd(&hist[(u >> shift) & 255], 1u);
        }
        __syncthreads();
        if (tid == 0) {
            int kk = s_kk, cum = 0, sel = 0;
            for (int bk = 255; bk >= 0; bk--) {
                int ct = (int)hist[bk];
                if (cum + ct >= kk) { sel = bk; s_kk = kk - cum; break; }
                cum += ct;
            }
            s_prefix = prefix | ((unsigned)sel << shift);
        }
        __syncthreads();
    }
    unsigned T = s_prefix;
    if (tid == 0) s_cnt = 0;
    __syncthreads();

    // collect all candidates >= threshold; pack (key, ~idx) for sort
    for (int i = tid; i < NPIX; i += 1024) {
        unsigned u = keys[i];
        if (u >= T) {
            int p = atomicAdd(&s_cnt, 1);
            if (p < 256)
                cand[p] = ((unsigned long long)u << 32) | (unsigned)(~(unsigned)i);
        }
    }
    __syncthreads();
    int cnt = min(s_cnt, 256);
    for (int i = cnt + tid; i < 256; i += 1024) cand[i] = 0ull;
    __syncthreads();

    // bitonic sort 256, descending (=> value desc, index asc on ties)
    for (int ksz = 2; ksz <= 256; ksz <<= 1) {
        for (int j = ksz >> 1; j > 0; j >>= 1) {
            for (int i = tid; i < 256; i += 1024) {
                int l = i ^ j;
                if (l > i) {
                    unsigned long long a = cand[i], c2 = cand[l];
                    bool dirDesc = ((i & ksz) == 0);
                    if ((a < c2) == dirDesc) { cand[i] = c2; cand[l] = a; }
                }
            }
            __syncthreads();
        }
    }
    if (tid < KDET)
        g_idx[b * KDET + tid] = (int)(~((unsigned)(cand[tid] & 0xFFFFFFFFull)));
}

// ---------------- MLP kernel: gather + 3-layer MLP, det & rec in one grid ----------------
__device__ __forceinline__ void run_layer(const float* __restrict__ Wg, float bj,
                                          const float* __restrict__ sin_,
                                          float* __restrict__ Wt, float acc[GTOK]) {
    int tid = threadIdx.x;
    #pragma unroll
    for (int t = 0; t < GTOK; t++) acc[t] = bj;
    for (int kc = 0; kc < 256; kc += 32) {
        // stage Wt[i][j] = W[j][kc+i], transposed, pad 257 -> conflict-free
        #pragma unroll
        for (int r = 0; r < 8; r++) {
            int e = (r * 256 + tid) * 4;
            int j2 = e >> 5, i = e & 31;
            float4 w4 = *reinterpret_cast<const float4*>(Wg + j2 * 256 + kc + i);
            Wt[(i + 0) * 257 + j2] = w4.x;
            Wt[(i + 1) * 257 + j2] = w4.y;
            Wt[(i + 2) * 257 + j2] = w4.z;
            Wt[(i + 3) * 257 + j2] = w4.w;
        }
        __syncthreads();
        float wr[32];
        #pragma unroll
        for (int i = 0; i < 32; i++) wr[i] = Wt[i * 257 + tid];
        #pragma unroll
        for (int t = 0; t < GTOK; t++) {
            const float4* iv = reinterpret_cast<const float4*>(sin_ + t * 256 + kc);
            float a = acc[t];
            #pragma unroll
            for (int q = 0; q < 8; q++) {
                float4 v = iv[q];
                a += v.x * wr[4 * q] + v.y * wr[4 * q + 1] + v.z * wr[4 * q + 2] + v.w * wr[4 * q + 3];
            }
            acc[t] = a;
        }
        __syncthreads();
    }
}

__global__ void __launch_bounds__(256) mlp_kernel(
    const float* __restrict__ x,
    const float* __restrict__ dW1, const float* __restrict__ db1,
    const float* __restrict__ dW2, const float* __restrict__ db2,
    const float* __restrict__ dW3, const float* __restrict__ db3,
    const float* __restrict__ rW1, const float* __restrict__ rb1,
    const float* __restrict__ rW2, const float* __restrict__ rb2,
    const float* __restrict__ rW3, const float* __restrict__ rb3,
    const float* __restrict__ det_q, const float* __restrict__ rec_q,
    float* __restrict__ out_det, float* __restrict__ out_rec) {
    extern __shared__ float sh[];
    float* bufA = sh;                  // [GTOK][256]
    float* bufB = sh + GTOK * 256;     // [GTOK][256]
    float* Wt   = sh + 2 * GTOK * 256; // [32][257]
    int tid = threadIdx.x;
    bool isDet = blockIdx.x < DET_BLOCKS;
    int blk = isDet ? blockIdx.x : (blockIdx.x - DET_BLOCKS);
    int kq = isDet ? KDET : KREC;

    // gather feat rows = x[b,:,idx] + pos[:,idx]
    #pragma unroll 4
    for (int t = 0; t < GTOK; t++) {
        int g = blk * GTOK + t;
        int b = g / kq, qi = g % kq;
        int idx = g_idx[b * KDET + qi];
        float v = __ldg(x + ((size_t)(b * CDIM + tid)) * NPIX + idx) + g_pos[tid * NPIX + idx];
        bufA[t * 256 + tid] = v;
    }
    __syncthreads();

    const float* W1 = isDet ? dW1 : rW1; const float* b1 = isDet ? db1 : rb1;
    const float* W2 = isDet ? dW2 : rW2; const float* b2 = isDet ? db2 : rb2;
    const float* W3 = isDet ? dW3 : rW3; const float* b3 = isDet ? db3 : rb3;

    float acc[GTOK];
    run_layer(W1, b1[tid], bufA, Wt, acc);
    #pragma unroll
    for (int t = 0; t < GTOK; t++) bufB[t * 256 + tid] = fmaxf(acc[t], 0.f);
    __syncthreads();

    run_layer(W2, b2[tid], bufB, Wt, acc);
    #pragma unroll
    for (int t = 0; t < GTOK; t++) bufA[t * 256 + tid] = fmaxf(acc[t], 0.f);
    __syncthreads();

    run_layer(W3, b3[tid], bufA, Wt, acc);
    #pragma unroll
    for (int t = 0; t < GTOK; t++) {
        int g = blk * GTOK + t;
        int qi = g % kq;
        if (isDet) out_det[(size_t)g * 256 + tid] = acc[t] + det_q[qi * 256 + tid];
        else       out_rec[(size_t)g * 256 + tid] = acc[t] + rec_q[qi * 256 + tid];
    }
}

// ---------------- launch ----------------
extern "C" void kernel_launch(void* const* d_in, const int* in_sizes, int n_in,
                              void* d_out, int out_size) {
    const float* x     = (const float*)d_in[0];
    const float* Wc    = (const float*)d_in[1];
    const float* bc    = (const float*)d_in[2];
    const float* Wb    = (const float*)d_in[3];
    const float* bb    = (const float*)d_in[4];
    const float* dW1   = (const float*)d_in[5];
    const float* db1   = (const float*)d_in[6];
    const float* dW2   = (const float*)d_in[7];
    const float* db2   = (const float*)d_in[8];
    const float* dW3   = (const float*)d_in[9];
    const float* db3   = (const float*)d_in[10];
    const float* rW1   = (const float*)d_in[11];
    const float* rb1   = (const float*)d_in[12];
    const float* rW2   = (const float*)d_in[13];
    const float* rb2   = (const float*)d_in[14];
    const float* rW3   = (const float*)d_in[15];
    const float* rb3   = (const float*)d_in[16];
    const float* det_q = (const float*)d_in[17];
    const float* rec_q = (const float*)d_in[18];
    const float* pe    = (const float*)d_in[19];

    float* out = (float*)d_out;
    float* out_det = out;                               // 16*100*256 = 409600
    float* out_rec = out + 409600;                      // 16*25*256  = 102400
    float* out_cls = out + 512000;                      // 16*10000*2 = 320000
    float* out_bb  = out + 832000;                      // 16*10000*4 = 640000

    pos_resize_kernel<<<(CDIM * NPIX + 255) / 256, 256>>>(pe);
    pos_proj_kernel<<<(NPIX + 255) / 256, 256>>>(Wc, Wb);
    main_pass_kernel<<<(BATCH * NPIX + 255) / 256, 256>>>(x, Wc, bc, Wb, bb, out_cls, out_bb);
    topk_kernel<<<BATCH, 1024>>>();

    int smem = (2 * GTOK * 256 + 32 * 257) * (int)sizeof(float);
    cudaFuncSetAttribute(mlp_kernel, cudaFuncAttributeMaxDynamicSharedMemorySize, smem);
    mlp_kernel<<<DET_BLOCKS + REC_BLOCKS, 256, smem>>>(
        x, dW1, db1, dW2, db2, dW3, db3,
        rW1, rb1, rW2, rb2, rW3, rb3,
        det_q, rec_q, out_det, out_rec);
}